// round 17
// baseline (speedup 1.0000x reference)
#include <cuda_runtime.h>
#include <math.h>

// Problem constants
#define Bv   16
#define Cv   64
#define Hv   256
#define Wv   256
#define Kv   7
#define HIDv 16
#define NCH  (Bv * Cv)          // 1024 channels
#define HWv  (Hv * Wv)          // 65536
#define KK   (Kv * Kv)          // 49
#define COLS (Cv * KK)          // 3136

// Conv tiling: persistent block over 4 vertical tiles of 128x32.
#define TILE_W 128
#define TILE_H 32
#define NT 4
#define CPT 4
#define RPT 4
#define IN_ROWS (RPT + 6)
#define SROWS (TILE_H + 6)       // 38
#define SSTRIDE 136              // smem col c holds global col x0-4+c

// Scratch (no cudaMalloc allowed)
__device__ float    g_psum4[NCH * 4];   // per-channel quadrant partial sums
__device__ float    g_wbuf[NCH * KK];   // generated conv weights
__device__ unsigned g_cnt[Bv];          // per-batch arrivals (256/replay; monotonic)
__device__ unsigned g_wdone[Bv];        // per-batch weight-ready epochs (monotonic)

// ---------------------------------------------------------------------------
// cp.async helpers + vectorized tile loader (R11, proven)
// ---------------------------------------------------------------------------
__device__ __forceinline__ int reflect_idx(int i) {
    return i < 0 ? -i : (i > 255 ? 510 - i : i);
}
__device__ __forceinline__ void cpasync4(float* dst_smem, const float* src_gmem) {
    unsigned dst = (unsigned)__cvta_generic_to_shared(dst_smem);
    asm volatile("cp.async.ca.shared.global [%0], [%1], 4;" :: "r"(dst), "l"(src_gmem));
}
__device__ __forceinline__ void cpasync16(float* dst_smem, const float* src_gmem) {
    unsigned dst = (unsigned)__cvta_generic_to_shared(dst_smem);
    asm volatile("cp.async.cg.shared.global [%0], [%1], 16;" :: "r"(dst), "l"(src_gmem));
}
__device__ __forceinline__ void load_tile_async(float* __restrict__ buf,
                                                const float* __restrict__ xc,
                                                int x0, int y0, int tx, int ty) {
    for (int r = ty; r < SROWS; r += 8) {
        const int gr = reflect_idx(y0 - 3 + r);
        const float* __restrict__ rowp = xc + gr * Wv;
        float* __restrict__ srow = buf + r * SSTRIDE;
        cpasync16(srow + 4 + 4 * tx, rowp + x0 + 4 * tx);
        if (tx < 6) {
            const int c = (tx < 3) ? (tx + 1) : (129 + tx);
            cpasync4(srow + c, rowp + reflect_idx(x0 - 4 + c));
        }
    }
}

// ---------------------------------------------------------------------------
// Conv compute (R11 structure — proven FP32 FMA floor)
// ---------------------------------------------------------------------------
template<int R>
__device__ __forceinline__ void conv_row_step(const float* __restrict__ row,
                                              const float (&w)[KK],
                                              float4 (&acc)[RPT]) {
    float v[12];
    {
        float4 t0 = *reinterpret_cast<const float4*>(row);
        float4 t1 = *reinterpret_cast<const float4*>(row + 4);
        float4 t2 = *reinterpret_cast<const float4*>(row + 8);
        v[0] = t0.x; v[1] = t0.y; v[2]  = t0.z; v[3]  = t0.w;
        v[4] = t1.x; v[5] = t1.y; v[6]  = t1.z; v[7]  = t1.w;
        v[8] = t2.x; v[9] = t2.y; v[10] = t2.z; v[11] = t2.w;
    }
    constexpr int OLO = (R > 6) ? (R - 6) : 0;
    constexpr int OHI = (R < RPT - 1) ? R : (RPT - 1);
    #pragma unroll
    for (int o = OLO; o <= OHI; ++o) {
        const int dy = R - o;
        #pragma unroll
        for (int dx = 0; dx < 7; ++dx) {
            const float wv = w[dy * 7 + dx];
            acc[o].x = fmaf(wv, v[dx + 1], acc[o].x);
            acc[o].y = fmaf(wv, v[dx + 2], acc[o].y);
            acc[o].z = fmaf(wv, v[dx + 3], acc[o].z);
            acc[o].w = fmaf(wv, v[dx + 4], acc[o].w);
        }
    }
}

template<int R>
__device__ __forceinline__ void conv_rows(const float* __restrict__ base,
                                          const float (&w)[KK],
                                          float4 (&acc)[RPT]) {
    conv_row_step<R>(base + R * SSTRIDE, w, acc);
    if constexpr (R + 1 < IN_ROWS)
        conv_rows<R + 1>(base, w, acc);
}

// ---------------------------------------------------------------------------
// FUSED kernel: quarter-GAP -> (last block per batch: MLP) -> spin -> conv.
// Grid (2,2,1024), block (32,8). Batch b = blocks [b*256, (b+1)*256) (contig).
// Wave 1 (>=296 blocks at occ 2) always covers batch 0 -> forward progress.
// ---------------------------------------------------------------------------
__global__ void __launch_bounds__(256, 2)
fused_kernel(const float* __restrict__ x,
             const float* __restrict__ w1, const float* __restrict__ b1,
             const float* __restrict__ w2, const float* __restrict__ b2,
             float* __restrict__ out) {
    __shared__ __align__(16) float buf0[SROWS * SSTRIDE];
    __shared__ __align__(16) float buf1[SROWS * SSTRIDE];
    __shared__ float wsh[KK];
    __shared__ float red[8];
    __shared__ unsigned myR_sh;
    __shared__ bool is_closer;
    __shared__ float sp[Cv];
    __shared__ float shh[HIDv];

    const int ch = blockIdx.z;
    const int batch = ch >> 6;
    const int tx = threadIdx.x, ty = threadIdx.y;
    const int tid = ty * 32 + tx;
    const int x0 = blockIdx.x * TILE_W;      // 0 or 128
    const int ybase = blockIdx.y * 128;      // 0 or 128

    const float* __restrict__ xc = x + (size_t)ch * HWv;

    // ---- Phase 1: sum own 128x128 quarter (exact, fixed-slot, no float atomics)
    {
        const float* __restrict__ xq = xc + (size_t)ybase * Wv + x0;
        float s = 0.f;
        #pragma unroll 4
        for (int i = tid; i < 128 * 32; i += 256) {
            const int r = i >> 5, c4 = i & 31;
            float4 v = *reinterpret_cast<const float4*>(xq + r * Wv + 4 * c4);
            s += (v.x + v.y) + (v.z + v.w);
        }
        #pragma unroll
        for (int off = 16; off > 0; off >>= 1)
            s += __shfl_xor_sync(0xffffffffu, s, off);
        if ((tid & 31) == 0) red[tid >> 5] = s;
        __syncthreads();
        if (tid == 0) {
            float t = 0.f;
            #pragma unroll
            for (int i = 0; i < 8; ++i) t += red[i];
            g_psum4[ch * 4 + (blockIdx.y * 2 + blockIdx.x)] = t;
            __threadfence();
            unsigned old = atomicAdd(&g_cnt[batch], 1u);
            myR_sh = (old >> 8) + 1u;                 // this replay's epoch
            is_closer = (((old + 1u) & 255u) == 0u);  // 256th arrival closes batch
        }
        __syncthreads();
    }

    // ---- Prologue: start streaming conv tile 0 (independent of weights)
    load_tile_async(buf0, xc, x0, ybase, tx, ty);
    asm volatile("cp.async.commit_group;");

    // ---- Closer block: compute this batch's MLP, publish weights
    if (is_closer) {
        __threadfence();   // acquire: all 1024 quadrant partials visible
        if (tid < Cv) {
            const float* q = &g_psum4[(batch * Cv + tid) * 4];
            sp[tid] = ((q[0] + q[1]) + (q[2] + q[3])) * (1.0f / (float)HWv);
        }
        __syncthreads();
        if (tid < HIDv) {
            float v = b1[tid];
            #pragma unroll
            for (int c = 0; c < Cv; ++c)
                v = fmaf(sp[c], w1[c * HIDv + tid], v);
            shh[tid] = 0.5f * v * (1.0f + erff(v * 0.70710678118654752f));
        }
        __syncthreads();
        float* __restrict__ wb = g_wbuf + (size_t)batch * COLS;
        for (int j = tid; j < COLS; j += 256) {
            float v = b2[j];
            #pragma unroll
            for (int h = 0; h < HIDv; ++h)
                v = fmaf(shh[h], w2[h * COLS + j], v);
            wb[j] = 1.0f / (1.0f + __expf(-v));
        }
        __syncthreads();
        if (tid == 0) {
            __threadfence();
            atomicAdd(&g_wdone[batch], 1u);
        }
    }

    // ---- Spin until this batch's weights exist for this replay
    if (tid == 0) {
        const unsigned target = myR_sh;
        while (*(volatile unsigned*)&g_wdone[batch] < target)
            __nanosleep(64);
        __threadfence();   // acquire
    }
    __syncthreads();

    if (tid < KK) wsh[tid] = g_wbuf[(size_t)ch * KK + tid];

    // ---- Conv over 4 vertical tiles (R11 double-buffered pipeline)
    float w[KK];
    const int col = tx * CPT;
    const int rbase = ty * RPT;

    #pragma unroll 1
    for (int t = 0; t < NT; ++t) {
        asm volatile("cp.async.wait_group 0;");
        __syncthreads();

        if (t == 0) {
            #pragma unroll
            for (int k = 0; k < KK; ++k) w[k] = wsh[k];
        }

        if (t + 1 < NT) {
            load_tile_async((t & 1) ? buf0 : buf1, xc, x0, ybase + (t + 1) * TILE_H, tx, ty);
            asm volatile("cp.async.commit_group;");
        }

        const float* __restrict__ cur = (t & 1) ? buf1 : buf0;

        float4 acc[RPT];
        #pragma unroll
        for (int o = 0; o < RPT; ++o) acc[o] = make_float4(0.f, 0.f, 0.f, 0.f);

        conv_rows<0>(&cur[rbase * SSTRIDE + col], w, acc);

        const int y0 = ybase + t * TILE_H;
        float* __restrict__ oc = out + (size_t)ch * HWv + (size_t)(y0 + rbase) * Wv + x0 + col;
        #pragma unroll
        for (int o = 0; o < RPT; ++o)
            *reinterpret_cast<float4*>(oc + o * Wv) = acc[o];
    }
}

// ---------------------------------------------------------------------------
// Launch: ONE kernel, default stream. No streams/events (alloc guard).
// ---------------------------------------------------------------------------
extern "C" void kernel_launch(void* const* d_in, const int* in_sizes, int n_in,
                              void* d_out, int out_size) {
    const float* x  = (const float*)d_in[0];
    const float* w1 = (const float*)d_in[1];
    const float* b1 = (const float*)d_in[2];
    const float* w2 = (const float*)d_in[3];
    const float* b2 = (const float*)d_in[4];
    float* out = (float*)d_out;

    fused_kernel<<<dim3(2, 2, NCH), dim3(32, 8)>>>(x, w1, b1, w2, b2, out);
}